// round 2
// baseline (speedup 1.0000x reference)
#include <cuda_runtime.h>
#include <cuda_bf16.h>
#include <math.h>

// Problem constants
#define BATCH 2
#define SLEN  2048
#define DMODEL 1024
#define NHEAD 16
#define HDIM  64          // DK == DV
#define NROWS (BATCH*SLEN)        // 4096
// scratch buffers (static device globals; no allocations allowed)
__device__ float g_Q[NROWS * DMODEL];
__device__ float g_K[NROWS * DMODEL];
__device__ float g_V[NROWS * DMODEL];
__device__ float g_A[NROWS * DMODEL];   // attention output [b,s,h*dv]

// ---------------------------------------------------------------------------
// SGEMM: C[M,N] = A[M,K] @ W[N,K]^T + bias[N]   (all fp32, row-major)
// Tiles: BM=BN=128, BK=8; 256 threads; 8x8 per-thread microtile.
// M,N multiples of 128; K multiple of 8.
// ---------------------------------------------------------------------------
__global__ __launch_bounds__(256) void sgemm_bias_kernel(
    const float* __restrict__ A, const float* __restrict__ W,
    const float* __restrict__ bias, float* __restrict__ C,
    int M, int N, int K)
{
    const int BM = 128, BN = 128, BK = 8;
    __shared__ float As[BK][BM];
    __shared__ float Bs[BK][BN];

    const int tid = threadIdx.x;
    const int bm = blockIdx.y * BM;
    const int bn = blockIdx.x * BN;
    const int lr = tid >> 1;          // 0..127 (row within tile for loads)
    const int lk = (tid & 1) * 4;     // 0 or 4 (k-offset for float4 load)
    const int tx = tid & 15;          // 0..15
    const int ty = tid >> 4;          // 0..15

    float acc[8][8];
#pragma unroll
    for (int i = 0; i < 8; i++)
#pragma unroll
        for (int j = 0; j < 8; j++) acc[i][j] = 0.f;

    const float* Aptr = A + (size_t)(bm + lr) * K + lk;
    const float* Wptr = W + (size_t)(bn + lr) * K + lk;

    for (int k0 = 0; k0 < K; k0 += BK) {
        float4 av = *(const float4*)(Aptr + k0);
        float4 wv = *(const float4*)(Wptr + k0);
        As[lk + 0][lr] = av.x; As[lk + 1][lr] = av.y;
        As[lk + 2][lr] = av.z; As[lk + 3][lr] = av.w;
        Bs[lk + 0][lr] = wv.x; Bs[lk + 1][lr] = wv.y;
        Bs[lk + 2][lr] = wv.z; Bs[lk + 3][lr] = wv.w;
        __syncthreads();
#pragma unroll
        for (int kk = 0; kk < BK; kk++) {
            float a[8], b[8];
#pragma unroll
            for (int i = 0; i < 8; i++) a[i] = As[kk][ty * 8 + i];
#pragma unroll
            for (int j = 0; j < 8; j++) b[j] = Bs[kk][tx * 8 + j];
#pragma unroll
            for (int i = 0; i < 8; i++)
#pragma unroll
                for (int j = 0; j < 8; j++)
                    acc[i][j] += a[i] * b[j];
        }
        __syncthreads();
    }

#pragma unroll
    for (int i = 0; i < 8; i++) {
        int row = bm + ty * 8 + i;
#pragma unroll
        for (int j = 0; j < 8; j += 4) {
            int col = bn + tx * 8 + j;
            float4 o;
            o.x = acc[i][j + 0] + bias[col + 0];
            o.y = acc[i][j + 1] + bias[col + 1];
            o.z = acc[i][j + 2] + bias[col + 2];
            o.w = acc[i][j + 3] + bias[col + 3];
            *(float4*)(C + (size_t)row * N + col) = o;
        }
    }
}

// ---------------------------------------------------------------------------
// Flash attention (fp32, online softmax), causal + key padding mask.
// Q,K,V layout: [B*S, NHEAD*HDIM], col = h*64 + d.
// Output O same layout (i.e., [b, s, h, dv]).
// Block: BQ=64 queries of one (b,h); loops over key tiles of BK_T=32.
// 128 threads: tx = tid%8 (0..7), ty = tid/8 (0..15).
//   S microtile: rows ty*4+[0..3], cols tx*4+[0..3]  (64x32)
//   O microtile: rows ty*4+[0..3], cols tx*8+[0..7]  (64x64)
// ---------------------------------------------------------------------------
#define BQ   64
#define BK_T 32

__global__ __launch_bounds__(128) void flash_attn_kernel(
    const float* __restrict__ Qg, const float* __restrict__ Kg,
    const float* __restrict__ Vg, const float* __restrict__ padm,
    float* __restrict__ Og)
{
    __shared__ float Qs[BQ][HDIM + 1];     // pad 65: conflict-free scalar reads
    __shared__ float Ks[BK_T][HDIM + 1];
    __shared__ float Vs[BK_T][HDIM + 4];   // pad 68: 16B-aligned float4 reads
    __shared__ float Ss[BQ][BK_T + 1];     // pad 33: row-major softmax conflict-free
    __shared__ float mS[BQ], lS[BQ], aS[BQ], padS[BK_T];

    const int tid = threadIdx.x;
    const int qt = blockIdx.x, h = blockIdx.y, b = blockIdx.z;
    const int q0 = qt * BQ;
    const int tx = tid & 7;     // 0..7
    const int ty = tid >> 3;    // 0..15
    const int r0 = ty * 4;

    const size_t rowbase = (size_t)b * SLEN;
    const int colq = h * HDIM;

    // Load Q tile (64 x 64) via float4
    for (int idx = tid; idx < BQ * (HDIM / 4); idx += 128) {
        int r  = idx >> 4;
        int d0 = (idx & 15) * 4;
        float4 v = *(const float4*)(Qg + (rowbase + q0 + r) * DMODEL + colq + d0);
        Qs[r][d0 + 0] = v.x; Qs[r][d0 + 1] = v.y;
        Qs[r][d0 + 2] = v.z; Qs[r][d0 + 3] = v.w;
    }
    if (tid < BQ) { mS[tid] = -1e30f; lS[tid] = 0.f; }

    float o_acc[4][8];
#pragma unroll
    for (int i = 0; i < 4; i++)
#pragma unroll
        for (int c = 0; c < 8; c++) o_acc[i][c] = 0.f;

    const int nkt = (q0 + BQ) / BK_T;   // causal: key tiles up to query tile end
    for (int kt = 0; kt < nkt; kt++) {
        const int k0 = kt * BK_T;
        __syncthreads();   // protect Ks/Vs/Ss/padS from previous iteration's readers

        // Load K,V tiles (32 x 64)
        for (int idx = tid; idx < BK_T * (HDIM / 4); idx += 128) {
            int r  = idx >> 4;
            int d0 = (idx & 15) * 4;
            size_t gro = (rowbase + k0 + r) * DMODEL + colq + d0;
            float4 kv = *(const float4*)(Kg + gro);
            Ks[r][d0 + 0] = kv.x; Ks[r][d0 + 1] = kv.y;
            Ks[r][d0 + 2] = kv.z; Ks[r][d0 + 3] = kv.w;
            float4 vv = *(const float4*)(Vg + gro);
            Vs[r][d0 + 0] = vv.x; Vs[r][d0 + 1] = vv.y;
            Vs[r][d0 + 2] = vv.z; Vs[r][d0 + 3] = vv.w;
        }
        if (tid < BK_T) {
            float p = padm[rowbase + k0 + tid];
            padS[tid] = (p > 0.f) ? -1e30f : 0.f;
        }
        __syncthreads();

        // S = Q @ K^T  (64x32), per-thread 4x4
        float s_acc[4][4];
#pragma unroll
        for (int i = 0; i < 4; i++)
#pragma unroll
            for (int j = 0; j < 4; j++) s_acc[i][j] = 0.f;
        const int c0 = tx * 4;
#pragma unroll
        for (int kk = 0; kk < HDIM; kk++) {
            float a[4], bb[4];
#pragma unroll
            for (int i = 0; i < 4; i++) a[i] = Qs[r0 + i][kk];
#pragma unroll
            for (int j = 0; j < 4; j++) bb[j] = Ks[c0 + j][kk];
#pragma unroll
            for (int i = 0; i < 4; i++)
#pragma unroll
                for (int j = 0; j < 4; j++)
                    s_acc[i][j] += a[i] * bb[j];
        }
        // write scaled + masked scores
#pragma unroll
        for (int i = 0; i < 4; i++) {
            int q = q0 + r0 + i;
#pragma unroll
            for (int j = 0; j < 4; j++) {
                int kc = c0 + j;
                int k  = k0 + kc;
                float s = s_acc[i][j] * 0.125f + padS[kc];
                if (k > q) s = -1e30f;
                Ss[r0 + i][kc] = s;
            }
        }
        __syncthreads();

        // Online softmax row update (one thread per query row)
        if (tid < BQ) {
            float mo = mS[tid];
            float mt = mo;
#pragma unroll
            for (int j = 0; j < BK_T; j++) mt = fmaxf(mt, Ss[tid][j]);
            float alpha = __expf(mo - mt);
            float sum = 0.f;
#pragma unroll
            for (int j = 0; j < BK_T; j++) {
                float p = __expf(Ss[tid][j] - mt);
                Ss[tid][j] = p;
                sum += p;
            }
            mS[tid] = mt;
            lS[tid] = lS[tid] * alpha + sum;
            aS[tid] = alpha;
        }
        __syncthreads();

        // Rescale accumulators and add P @ V
#pragma unroll
        for (int i = 0; i < 4; i++) {
            float al = aS[r0 + i];
#pragma unroll
            for (int c = 0; c < 8; c++) o_acc[i][c] *= al;
        }
        const int co = tx * 8;
#pragma unroll
        for (int kk = 0; kk < BK_T; kk++) {
            float4 v0 = *(const float4*)&Vs[kk][co];
            float4 v1 = *(const float4*)&Vs[kk][co + 4];
            float p[4];
#pragma unroll
            for (int i = 0; i < 4; i++) p[i] = Ss[r0 + i][kk];
#pragma unroll
            for (int i = 0; i < 4; i++) {
                o_acc[i][0] += p[i] * v0.x;
                o_acc[i][1] += p[i] * v0.y;
                o_acc[i][2] += p[i] * v0.z;
                o_acc[i][3] += p[i] * v0.w;
                o_acc[i][4] += p[i] * v1.x;
                o_acc[i][5] += p[i] * v1.y;
                o_acc[i][6] += p[i] * v1.z;
                o_acc[i][7] += p[i] * v1.w;
            }
        }
    }

    // Epilogue: normalize and store
    const int co = tx * 8;
#pragma unroll
    for (int i = 0; i < 4; i++) {
        float inv = 1.f / lS[r0 + i];
        float* op = Og + (rowbase + q0 + r0 + i) * DMODEL + colq + co;
        float4 o0, o1;
        o0.x = o_acc[i][0] * inv; o0.y = o_acc[i][1] * inv;
        o0.z = o_acc[i][2] * inv; o0.w = o_acc[i][3] * inv;
        o1.x = o_acc[i][4] * inv; o1.y = o_acc[i][5] * inv;
        o1.z = o_acc[i][6] * inv; o1.w = o_acc[i][7] * inv;
        *(float4*)(op)     = o0;
        *(float4*)(op + 4) = o1;
    }
}

// ---------------------------------------------------------------------------
extern "C" void kernel_launch(void* const* d_in, const int* in_sizes, int n_in,
                              void* d_out, int out_size)
{
    const float* input = (const float*)d_in[0];
    const float* padm  = (const float*)d_in[1];
    const float* wq_w  = (const float*)d_in[2];
    const float* wq_b  = (const float*)d_in[3];
    const float* wk_w  = (const float*)d_in[4];
    const float* wk_b  = (const float*)d_in[5];
    const float* wv_w  = (const float*)d_in[6];
    const float* wv_b  = (const float*)d_in[7];
    const float* fin_w = (const float*)d_in[8];
    const float* fin_b = (const float*)d_in[9];
    float* out = (float*)d_out;

    float *Qp, *Kp, *Vp, *Ap;
    cudaGetSymbolAddress((void**)&Qp, g_Q);
    cudaGetSymbolAddress((void**)&Kp, g_K);
    cudaGetSymbolAddress((void**)&Vp, g_V);
    cudaGetSymbolAddress((void**)&Ap, g_A);

    dim3 gemm_grid(DMODEL / 128, NROWS / 128);  // (8, 32)

    // QKV projections
    sgemm_bias_kernel<<<gemm_grid, 256>>>(input, wq_w, wq_b, Qp, NROWS, DMODEL, DMODEL);
    sgemm_bias_kernel<<<gemm_grid, 256>>>(input, wk_w, wk_b, Kp, NROWS, DMODEL, DMODEL);
    sgemm_bias_kernel<<<gemm_grid, 256>>>(input, wv_w, wv_b, Vp, NROWS, DMODEL, DMODEL);

    // Causal attention
    dim3 attn_grid(SLEN / BQ, NHEAD, BATCH);   // (32, 16, 2)
    flash_attn_kernel<<<attn_grid, 128>>>(Qp, Kp, Vp, padm, Ap);

    // Output projection
    sgemm_bias_kernel<<<gemm_grid, 256>>>(Ap, fin_w, fin_b, out, NROWS, DMODEL, DMODEL);
}

// round 7
// speedup vs baseline: 1.7252x; 1.7252x over previous
#include <cuda_runtime.h>
#include <cuda_fp16.h>
#include <cuda_bf16.h>
#include <math.h>
#include <stdint.h>

// Problem constants
#define BATCH 2
#define SLEN  2048
#define DMODEL 1024
#define NHEAD 16
#define HDIM  64          // DK == DV
#define NROWS (BATCH*SLEN)        // 4096

// scratch buffers (static device globals; no allocations allowed)
__device__ float g_Q[NROWS * DMODEL];
__device__ float g_K[NROWS * DMODEL];
__device__ float g_V[NROWS * DMODEL];
__device__ float g_A[NROWS * DMODEL];   // attention output [b,s,h*dv]

__device__ __forceinline__ uint32_t smem_u32(const void* p) {
    uint32_t a;
    asm("{ .reg .u64 t; cvta.to.shared.u64 t, %1; cvt.u32.u64 %0, t; }"
        : "=r"(a) : "l"(p));
    return a;
}

__device__ __forceinline__ void ldmatrix_x4(uint32_t& r0, uint32_t& r1,
                                            uint32_t& r2, uint32_t& r3,
                                            uint32_t addr) {
    asm volatile("ldmatrix.sync.aligned.m8n8.x4.shared.b16 {%0,%1,%2,%3}, [%4];"
                 : "=r"(r0), "=r"(r1), "=r"(r2), "=r"(r3) : "r"(addr));
}

__device__ __forceinline__ void mma_16816(float* d, const uint32_t* a,
                                          uint32_t b0, uint32_t b1) {
    asm volatile(
        "mma.sync.aligned.m16n8k16.row.col.f32.f16.f16.f32 "
        "{%0,%1,%2,%3}, {%4,%5,%6,%7}, {%8,%9}, {%0,%1,%2,%3};"
        : "+f"(d[0]), "+f"(d[1]), "+f"(d[2]), "+f"(d[3])
        : "r"(a[0]), "r"(a[1]), "r"(a[2]), "r"(a[3]), "r"(b0), "r"(b1));
}

// ===========================================================================
// HGEMM via mma.sync (fp16 in, fp32 accum): C[M,N] = A[M,K] @ W[N,K]^T + bias
// CTA 128x128, 256 threads (2x4 warps, 64x32 per warp), BK=32.
// fp32 gmem inputs converted to f16 during smem staging.
// ===========================================================================
#define BKK 32
#define KPAD 40   // 32 + 8 halves; 80B row stride (16B aligned, ldmatrix conflict-free)

__global__ __launch_bounds__(256) void hgemm_mma_kernel(
    const float* __restrict__ A, const float* __restrict__ W,
    const float* __restrict__ bias, float* __restrict__ C,
    int M, int N, int K)
{
    __shared__ __half As[128][KPAD];
    __shared__ __half Ws[128][KPAD];

    const int tid = threadIdx.x;
    const int wid = tid >> 5;
    const int l   = tid & 31;
    const int bn = blockIdx.x * 128;
    const int bm = blockIdx.y * 128;

    const int wm = wid & 1;          // 0..1
    const int wn = wid >> 1;         // 0..3
    const int m_base = wm * 64;
    const int n_base = wn * 32;

    // Staging indices: each thread converts one row-half (16 floats)
    const int sr = tid >> 1;          // 0..127
    const int sk = (tid & 1) * 16;    // 0 or 16

    // ldmatrix lane addresses
    const int arow = m_base + (l & 7) + 8 * ((l >> 3) & 1);
    const int acol = (l >> 4) * 8;
    uint32_t a_addr[4];
#pragma unroll
    for (int mt = 0; mt < 4; mt++)
        a_addr[mt] = smem_u32(&As[arow + mt * 16][acol]);

    const int brow = n_base + (l & 7) + 8 * (l >> 4);
    const int bcol = ((l >> 3) & 1) * 8;
    uint32_t b_addr[2];
#pragma unroll
    for (int np = 0; np < 2; np++)
        b_addr[np] = smem_u32(&Ws[brow + np * 16][bcol]);

    float acc[4][4][4];
#pragma unroll
    for (int mt = 0; mt < 4; mt++)
#pragma unroll
        for (int nt = 0; nt < 4; nt++)
#pragma unroll
            for (int i = 0; i < 4; i++) acc[mt][nt][i] = 0.f;

    const float* Ap = A + (size_t)(bm + sr) * K + sk;
    const float* Wp = W + (size_t)(bn + sr) * K + sk;

    for (int k0 = 0; k0 < K; k0 += BKK) {
        // stage + convert 128x32 fp32 -> f16 for A and W
        {
            float4 f0 = *(const float4*)(Ap + k0 + 0);
            float4 f1 = *(const float4*)(Ap + k0 + 4);
            float4 f2 = *(const float4*)(Ap + k0 + 8);
            float4 f3 = *(const float4*)(Ap + k0 + 12);
            float4 g0 = *(const float4*)(Wp + k0 + 0);
            float4 g1 = *(const float4*)(Wp + k0 + 4);
            float4 g2 = *(const float4*)(Wp + k0 + 8);
            float4 g3 = *(const float4*)(Wp + k0 + 12);
            __half2 h[8];
            h[0] = __floats2half2_rn(f0.x, f0.y); h[1] = __floats2half2_rn(f0.z, f0.w);
            h[2] = __floats2half2_rn(f1.x, f1.y); h[3] = __floats2half2_rn(f1.z, f1.w);
            h[4] = __floats2half2_rn(f2.x, f2.y); h[5] = __floats2half2_rn(f2.z, f2.w);
            h[6] = __floats2half2_rn(f3.x, f3.y); h[7] = __floats2half2_rn(f3.z, f3.w);
            *(uint4*)&As[sr][sk]     = *(uint4*)&h[0];
            *(uint4*)&As[sr][sk + 8] = *(uint4*)&h[4];
            h[0] = __floats2half2_rn(g0.x, g0.y); h[1] = __floats2half2_rn(g0.z, g0.w);
            h[2] = __floats2half2_rn(g1.x, g1.y); h[3] = __floats2half2_rn(g1.z, g1.w);
            h[4] = __floats2half2_rn(g2.x, g2.y); h[5] = __floats2half2_rn(g2.z, g2.w);
            h[6] = __floats2half2_rn(g3.x, g3.y); h[7] = __floats2half2_rn(g3.z, g3.w);
            *(uint4*)&Ws[sr][sk]     = *(uint4*)&h[0];
            *(uint4*)&Ws[sr][sk + 8] = *(uint4*)&h[4];
        }
        __syncthreads();

#pragma unroll
        for (int ks = 0; ks < 2; ks++) {
            const uint32_t koff = ks * 32;   // 16 halves = 32 bytes
            uint32_t af[4][4];
#pragma unroll
            for (int mt = 0; mt < 4; mt++)
                ldmatrix_x4(af[mt][0], af[mt][1], af[mt][2], af[mt][3],
                            a_addr[mt] + koff);
            uint32_t bf[2][4];
#pragma unroll
            for (int np = 0; np < 2; np++)
                ldmatrix_x4(bf[np][0], bf[np][1], bf[np][2], bf[np][3],
                            b_addr[np] + koff);
#pragma unroll
            for (int mt = 0; mt < 4; mt++)
#pragma unroll
                for (int nt = 0; nt < 4; nt++) {
                    const int np = nt >> 1, hh = (nt & 1) * 2;
                    mma_16816(acc[mt][nt], af[mt], bf[np][hh], bf[np][hh + 1]);
                }
        }
        __syncthreads();
    }

    // Epilogue: bias + store fp32
    const int rl = l >> 2;
    const int cl = (l & 3) * 2;
#pragma unroll
    for (int mt = 0; mt < 4; mt++) {
#pragma unroll
        for (int nt = 0; nt < 4; nt++) {
            const int row = bm + m_base + mt * 16 + rl;
            const int col = bn + n_base + nt * 8 + cl;
            const float b0 = bias[col], b1 = bias[col + 1];
            float2 o0, o1;
            o0.x = acc[mt][nt][0] + b0; o0.y = acc[mt][nt][1] + b1;
            o1.x = acc[mt][nt][2] + b0; o1.y = acc[mt][nt][3] + b1;
            *(float2*)(C + (size_t)row * N + col)       = o0;
            *(float2*)(C + (size_t)(row + 8) * N + col) = o1;
        }
    }
}

// ---------------------------------------------------------------------------
// Flash attention (fp32, online softmax), causal + key padding mask.
// (unchanged — known good, 810us; tensor-core version is next round's target)
// ---------------------------------------------------------------------------
#define BQ   64
#define BK_T 32

__global__ __launch_bounds__(128) void flash_attn_kernel(
    const float* __restrict__ Qg, const float* __restrict__ Kg,
    const float* __restrict__ Vg, const float* __restrict__ padm,
    float* __restrict__ Og)
{
    __shared__ float Qs[BQ][HDIM + 1];
    __shared__ float Ks[BK_T][HDIM + 1];
    __shared__ float Vs[BK_T][HDIM + 4];
    __shared__ float Ss[BQ][BK_T + 1];
    __shared__ float mS[BQ], lS[BQ], aS[BQ], padS[BK_T];

    const int tid = threadIdx.x;
    const int qt = blockIdx.x, h = blockIdx.y, b = blockIdx.z;
    const int q0 = qt * BQ;
    const int tx = tid & 7;
    const int ty = tid >> 3;
    const int r0 = ty * 4;

    const size_t rowbase = (size_t)b * SLEN;
    const int colq = h * HDIM;

    for (int idx = tid; idx < BQ * (HDIM / 4); idx += 128) {
        int r  = idx >> 4;
        int d0 = (idx & 15) * 4;
        float4 v = *(const float4*)(Qg + (rowbase + q0 + r) * DMODEL + colq + d0);
        Qs[r][d0 + 0] = v.x; Qs[r][d0 + 1] = v.y;
        Qs[r][d0 + 2] = v.z; Qs[r][d0 + 3] = v.w;
    }
    if (tid < BQ) { mS[tid] = -1e30f; lS[tid] = 0.f; }

    float o_acc[4][8];
#pragma unroll
    for (int i = 0; i < 4; i++)
#pragma unroll
        for (int c = 0; c < 8; c++) o_acc[i][c] = 0.f;

    const int nkt = (q0 + BQ) / BK_T;
    for (int kt = 0; kt < nkt; kt++) {
        const int k0 = kt * BK_T;
        __syncthreads();

        for (int idx = tid; idx < BK_T * (HDIM / 4); idx += 128) {
            int r  = idx >> 4;
            int d0 = (idx & 15) * 4;
            size_t gro = (rowbase + k0 + r) * DMODEL + colq + d0;
            float4 kv = *(const float4*)(Kg + gro);
            Ks[r][d0 + 0] = kv.x; Ks[r][d0 + 1] = kv.y;
            Ks[r][d0 + 2] = kv.z; Ks[r][d0 + 3] = kv.w;
            float4 vv = *(const float4*)(Vg + gro);
            Vs[r][d0 + 0] = vv.x; Vs[r][d0 + 1] = vv.y;
            Vs[r][d0 + 2] = vv.z; Vs[r][d0 + 3] = vv.w;
        }
        if (tid < BK_T) {
            float p = padm[rowbase + k0 + tid];
            padS[tid] = (p > 0.f) ? -1e30f : 0.f;
        }
        __syncthreads();

        float s_acc[4][4];
#pragma unroll
        for (int i = 0; i < 4; i++)
#pragma unroll
            for (int j = 0; j < 4; j++) s_acc[i][j] = 0.f;
        const int c0 = tx * 4;
#pragma unroll
        for (int kk = 0; kk < HDIM; kk++) {
            float a[4], bb[4];
#pragma unroll
            for (int i = 0; i < 4; i++) a[i] = Qs[r0 + i][kk];
#pragma unroll
            for (int j = 0; j < 4; j++) bb[j] = Ks[c0 + j][kk];
#pragma unroll
            for (int i = 0; i < 4; i++)
#pragma unroll
                for (int j = 0; j < 4; j++)
                    s_acc[i][j] += a[i] * bb[j];
        }
#pragma unroll
        for (int i = 0; i < 4; i++) {
            int q = q0 + r0 + i;
#pragma unroll
            for (int j = 0; j < 4; j++) {
                int kc = c0 + j;
                int k  = k0 + kc;
                float s = s_acc[i][j] * 0.125f + padS[kc];
                if (k > q) s = -1e30f;
                Ss[r0 + i][kc] = s;
            }
        }
        __syncthreads();

        if (tid < BQ) {
            float mo = mS[tid];
            float mt = mo;
#pragma unroll
            for (int j = 0; j < BK_T; j++) mt = fmaxf(mt, Ss[tid][j]);
            float alpha = __expf(mo - mt);
            float sum = 0.f;
#pragma unroll
            for (int j = 0; j < BK_T; j++) {
                float p = __expf(Ss[tid][j] - mt);
                Ss[tid][j] = p;
                sum += p;
            }
            mS[tid] = mt;
            lS[tid] = lS[tid] * alpha + sum;
            aS[tid] = alpha;
        }
        __syncthreads();

#pragma unroll
        for (int i = 0; i < 4; i++) {
            float al = aS[r0 + i];
#pragma unroll
            for (int c = 0; c < 8; c++) o_acc[i][c] *= al;
        }
        const int co = tx * 8;
#pragma unroll
        for (int kk = 0; kk < BK_T; kk++) {
            float4 v0 = *(const float4*)&Vs[kk][co];
            float4 v1 = *(const float4*)&Vs[kk][co + 4];
            float p[4];
#pragma unroll
            for (int i = 0; i < 4; i++) p[i] = Ss[r0 + i][kk];
#pragma unroll
            for (int i = 0; i < 4; i++) {
                o_acc[i][0] += p[i] * v0.x;
                o_acc[i][1] += p[i] * v0.y;
                o_acc[i][2] += p[i] * v0.z;
                o_acc[i][3] += p[i] * v0.w;
                o_acc[i][4] += p[i] * v1.x;
                o_acc[i][5] += p[i] * v1.y;
                o_acc[i][6] += p[i] * v1.z;
                o_acc[i][7] += p[i] * v1.w;
            }
        }
    }

    const int co = tx * 8;
#pragma unroll
    for (int i = 0; i < 4; i++) {
        float inv = 1.f / lS[r0 + i];
        float* op = Og + (rowbase + q0 + r0 + i) * DMODEL + colq + co;
        float4 o0, o1;
        o0.x = o_acc[i][0] * inv; o0.y = o_acc[i][1] * inv;
        o0.z = o_acc[i][2] * inv; o0.w = o_acc[i][3] * inv;
        o1.x = o_acc[i][4] * inv; o1.y = o_acc[i][5] * inv;
        o1.z = o_acc[i][6] * inv; o1.w = o_acc[i][7] * inv;
        *(float4*)(op)     = o0;
        *(float4*)(op + 4) = o1;
    }
}

// ---------------------------------------------------------------------------
extern "C" void kernel_launch(void* const* d_in, const int* in_sizes, int n_in,
                              void* d_out, int out_size)
{
    const float* input = (const float*)d_in[0];
    const float* padm  = (const float*)d_in[1];
    const float* wq_w  = (const float*)d_in[2];
    const float* wq_b  = (const float*)d_in[3];
    const float* wk_w  = (const float*)d_in[4];
    const float* wk_b  = (const float*)d_in[5];
    const float* wv_w  = (const float*)d_in[6];
    const float* wv_b  = (const float*)d_in[7];
    const float* fin_w = (const float*)d_in[8];
    const float* fin_b = (const float*)d_in[9];
    float* out = (float*)d_out;

    float *Qp, *Kp, *Vp, *Ap;
    cudaGetSymbolAddress((void**)&Qp, g_Q);
    cudaGetSymbolAddress((void**)&Kp, g_K);
    cudaGetSymbolAddress((void**)&Vp, g_V);
    cudaGetSymbolAddress((void**)&Ap, g_A);

    dim3 gemm_grid(DMODEL / 128, NROWS / 128);  // (8, 32)

    // QKV projections (fp16 mma.sync tensor-core)
    hgemm_mma_kernel<<<gemm_grid, 256>>>(input, wq_w, wq_b, Qp, NROWS, DMODEL, DMODEL);
    hgemm_mma_kernel<<<gemm_grid, 256>>>(input, wk_w, wk_b, Kp, NROWS, DMODEL, DMODEL);
    hgemm_mma_kernel<<<gemm_grid, 256>>>(input, wv_w, wv_b, Vp, NROWS, DMODEL, DMODEL);

    // Causal attention (fp32)
    dim3 attn_grid(SLEN / BQ, NHEAD, BATCH);   // (32, 16, 2)
    flash_attn_kernel<<<attn_grid, 128>>>(Qp, Kp, Vp, padm, Ap);

    // Output projection (fp16 mma.sync tensor-core)
    hgemm_mma_kernel<<<gemm_grid, 256>>>(Ap, fin_w, fin_b, out, NROWS, DMODEL, DMODEL);
}

// round 9
// speedup vs baseline: 3.4731x; 2.0132x over previous
#include <cuda_runtime.h>
#include <cuda_fp16.h>
#include <cuda_bf16.h>
#include <math.h>
#include <stdint.h>

// Problem constants
#define BATCH 2
#define SLEN  2048
#define DMODEL 1024
#define NHEAD 16
#define HDIM  64          // DK == DV
#define NROWS (BATCH*SLEN)        // 4096

// scratch buffers (static device globals; no allocations allowed)
__device__ float g_Q[NROWS * DMODEL];
__device__ float g_K[NROWS * DMODEL];
__device__ float g_V[NROWS * DMODEL];
__device__ float g_A[NROWS * DMODEL];   // attention output [b,s,h*dv]

__device__ __forceinline__ uint32_t smem_u32(const void* p) {
    uint32_t a;
    asm("{ .reg .u64 t; cvta.to.shared.u64 t, %1; cvt.u32.u64 %0, t; }"
        : "=r"(a) : "l"(p));
    return a;
}

__device__ __forceinline__ void ldmatrix_x4(uint32_t& r0, uint32_t& r1,
                                            uint32_t& r2, uint32_t& r3,
                                            uint32_t addr) {
    asm volatile("ldmatrix.sync.aligned.m8n8.x4.shared.b16 {%0,%1,%2,%3}, [%4];"
                 : "=r"(r0), "=r"(r1), "=r"(r2), "=r"(r3) : "r"(addr));
}

__device__ __forceinline__ void ldmatrix_x4_trans(uint32_t& r0, uint32_t& r1,
                                                  uint32_t& r2, uint32_t& r3,
                                                  uint32_t addr) {
    asm volatile("ldmatrix.sync.aligned.m8n8.x4.trans.shared.b16 {%0,%1,%2,%3}, [%4];"
                 : "=r"(r0), "=r"(r1), "=r"(r2), "=r"(r3) : "r"(addr));
}

__device__ __forceinline__ void mma_16816(float* d, const uint32_t* a,
                                          uint32_t b0, uint32_t b1) {
    asm volatile(
        "mma.sync.aligned.m16n8k16.row.col.f32.f16.f16.f32 "
        "{%0,%1,%2,%3}, {%4,%5,%6,%7}, {%8,%9}, {%0,%1,%2,%3};"
        : "+f"(d[0]), "+f"(d[1]), "+f"(d[2]), "+f"(d[3])
        : "r"(a[0]), "r"(a[1]), "r"(a[2]), "r"(a[3]), "r"(b0), "r"(b1));
}

// ===========================================================================
// HGEMM via mma.sync (fp16 in, fp32 accum): C[M,N] = A[M,K] @ W[N,K]^T + bias
// (unchanged — verified R7)
// ===========================================================================
#define BKK 32
#define KPAD 40   // 80B row stride

__global__ __launch_bounds__(256) void hgemm_mma_kernel(
    const float* __restrict__ A, const float* __restrict__ W,
    const float* __restrict__ bias, float* __restrict__ C,
    int M, int N, int K)
{
    __shared__ __half As[128][KPAD];
    __shared__ __half Ws[128][KPAD];

    const int tid = threadIdx.x;
    const int wid = tid >> 5;
    const int l   = tid & 31;
    const int bn = blockIdx.x * 128;
    const int bm = blockIdx.y * 128;

    const int wm = wid & 1;
    const int wn = wid >> 1;
    const int m_base = wm * 64;
    const int n_base = wn * 32;

    const int sr = tid >> 1;
    const int sk = (tid & 1) * 16;

    const int arow = m_base + (l & 7) + 8 * ((l >> 3) & 1);
    const int acol = (l >> 4) * 8;
    uint32_t a_addr[4];
#pragma unroll
    for (int mt = 0; mt < 4; mt++)
        a_addr[mt] = smem_u32(&As[arow + mt * 16][acol]);

    const int brow = n_base + (l & 7) + 8 * (l >> 4);
    const int bcol = ((l >> 3) & 1) * 8;
    uint32_t b_addr[2];
#pragma unroll
    for (int np = 0; np < 2; np++)
        b_addr[np] = smem_u32(&Ws[brow + np * 16][bcol]);

    float acc[4][4][4];
#pragma unroll
    for (int mt = 0; mt < 4; mt++)
#pragma unroll
        for (int nt = 0; nt < 4; nt++)
#pragma unroll
            for (int i = 0; i < 4; i++) acc[mt][nt][i] = 0.f;

    const float* Ap = A + (size_t)(bm + sr) * K + sk;
    const float* Wp = W + (size_t)(bn + sr) * K + sk;

    for (int k0 = 0; k0 < K; k0 += BKK) {
        {
            float4 f0 = *(const float4*)(Ap + k0 + 0);
            float4 f1 = *(const float4*)(Ap + k0 + 4);
            float4 f2 = *(const float4*)(Ap + k0 + 8);
            float4 f3 = *(const float4*)(Ap + k0 + 12);
            float4 g0 = *(const float4*)(Wp + k0 + 0);
            float4 g1 = *(const float4*)(Wp + k0 + 4);
            float4 g2 = *(const float4*)(Wp + k0 + 8);
            float4 g3 = *(const float4*)(Wp + k0 + 12);
            __half2 h[8];
            h[0] = __floats2half2_rn(f0.x, f0.y); h[1] = __floats2half2_rn(f0.z, f0.w);
            h[2] = __floats2half2_rn(f1.x, f1.y); h[3] = __floats2half2_rn(f1.z, f1.w);
            h[4] = __floats2half2_rn(f2.x, f2.y); h[5] = __floats2half2_rn(f2.z, f2.w);
            h[6] = __floats2half2_rn(f3.x, f3.y); h[7] = __floats2half2_rn(f3.z, f3.w);
            *(uint4*)&As[sr][sk]     = *(uint4*)&h[0];
            *(uint4*)&As[sr][sk + 8] = *(uint4*)&h[4];
            h[0] = __floats2half2_rn(g0.x, g0.y); h[1] = __floats2half2_rn(g0.z, g0.w);
            h[2] = __floats2half2_rn(g1.x, g1.y); h[3] = __floats2half2_rn(g1.z, g1.w);
            h[4] = __floats2half2_rn(g2.x, g2.y); h[5] = __floats2half2_rn(g2.z, g2.w);
            h[6] = __floats2half2_rn(g3.x, g3.y); h[7] = __floats2half2_rn(g3.z, g3.w);
            *(uint4*)&Ws[sr][sk]     = *(uint4*)&h[0];
            *(uint4*)&Ws[sr][sk + 8] = *(uint4*)&h[4];
        }
        __syncthreads();

#pragma unroll
        for (int ks = 0; ks < 2; ks++) {
            const uint32_t koff = ks * 32;
            uint32_t af[4][4];
#pragma unroll
            for (int mt = 0; mt < 4; mt++)
                ldmatrix_x4(af[mt][0], af[mt][1], af[mt][2], af[mt][3],
                            a_addr[mt] + koff);
            uint32_t bf[2][4];
#pragma unroll
            for (int np = 0; np < 2; np++)
                ldmatrix_x4(bf[np][0], bf[np][1], bf[np][2], bf[np][3],
                            b_addr[np] + koff);
#pragma unroll
            for (int mt = 0; mt < 4; mt++)
#pragma unroll
                for (int nt = 0; nt < 4; nt++) {
                    const int np = nt >> 1, hh = (nt & 1) * 2;
                    mma_16816(acc[mt][nt], af[mt], bf[np][hh], bf[np][hh + 1]);
                }
        }
        __syncthreads();
    }

    const int rl = l >> 2;
    const int cl = (l & 3) * 2;
#pragma unroll
    for (int mt = 0; mt < 4; mt++) {
#pragma unroll
        for (int nt = 0; nt < 4; nt++) {
            const int row = bm + m_base + mt * 16 + rl;
            const int col = bn + n_base + nt * 8 + cl;
            const float b0 = bias[col], b1 = bias[col + 1];
            float2 o0, o1;
            o0.x = acc[mt][nt][0] + b0; o0.y = acc[mt][nt][1] + b1;
            o1.x = acc[mt][nt][2] + b0; o1.y = acc[mt][nt][3] + b1;
            *(float2*)(C + (size_t)row * N + col)       = o0;
            *(float2*)(C + (size_t)(row + 8) * N + col) = o1;
        }
    }
}

// ===========================================================================
// Tensor-core flash attention (f16 mma, fp32 accum, register softmax).
// CTA: 64 queries of one (b,h); 128 threads; warp w owns query rows w*16..+15.
// Key tiles of 64. Q@K^T and P@V both m16n8k16.
// ===========================================================================
#define FPAD 72   // 144B row stride: rows hit banks 4i mod 32 (conflict-free)

__global__ __launch_bounds__(128) void flash_attn_mma_kernel(
    const float* __restrict__ Qg, const float* __restrict__ Kg,
    const float* __restrict__ Vg, const float* __restrict__ padm,
    float* __restrict__ Og)
{
    __shared__ __half Qs[64][FPAD];
    __shared__ __half Ks[64][FPAD];
    __shared__ __half Vs[64][FPAD];
    __shared__ float padS[64];

    const int tid = threadIdx.x;
    const int w = tid >> 5;
    const int l = tid & 31;
    const int qt = blockIdx.x, h = blockIdx.y, b = blockIdx.z;
    const int q0 = qt * 64;
    const size_t rowbase = (size_t)b * SLEN;
    const int colq = h * HDIM;

    // ---- stage Q tile (64x64 fp32 -> f16) ----
    {
        const int r = tid >> 1, c0 = (tid & 1) * 32;
        const float* src = Qg + (rowbase + q0 + r) * DMODEL + colq + c0;
        __half2 hbuf[16];
#pragma unroll
        for (int i = 0; i < 8; i++) {
            float4 f = *(const float4*)(src + i * 4);
            hbuf[2 * i]     = __floats2half2_rn(f.x, f.y);
            hbuf[2 * i + 1] = __floats2half2_rn(f.z, f.w);
        }
#pragma unroll
        for (int i = 0; i < 4; i++)
            *(uint4*)&Qs[r][c0 + i * 8] = *(uint4*)&hbuf[i * 4];
    }
    __syncthreads();

    // fragment lane addresses
    const int frow = (l & 7) + 8 * ((l >> 3) & 1);   // A & V-trans row pattern
    const int fcol = (l >> 4) * 8;
    const uint32_t q_addr = smem_u32(&Qs[w * 16 + frow][fcol]);
    const int brow = (l & 7) + 8 * (l >> 4);          // K (non-trans B) row pattern
    const int bcol = ((l >> 3) & 1) * 8;

    // Q fragments (invariant): aq[kc][4]
    uint32_t aq[4][4];
#pragma unroll
    for (int kc = 0; kc < 4; kc++)
        ldmatrix_x4(aq[kc][0], aq[kc][1], aq[kc][2], aq[kc][3],
                    q_addr + kc * 32);

    float oacc[8][4];
#pragma unroll
    for (int nt = 0; nt < 8; nt++)
#pragma unroll
        for (int i = 0; i < 4; i++) oacc[nt][i] = 0.f;
    float m_r[2] = {-1e30f, -1e30f};
    float l_r[2] = {0.f, 0.f};

    const int qlo = q0 + w * 16 + (l >> 2);
    const int qhi = qlo + 8;

    for (int kt = 0; kt <= qt; kt++) {
        const int k0 = kt * 64;
        __syncthreads();   // protect Ks/Vs/padS from previous iteration readers

        // ---- stage K,V tiles (64x64 fp32 -> f16 each) ----
        {
            const int r = tid >> 1, c0 = (tid & 1) * 32;
            const size_t gro = (rowbase + k0 + r) * DMODEL + colq + c0;
            const float* ks = Kg + gro;
            const float* vs = Vg + gro;
            __half2 hbuf[16];
#pragma unroll
            for (int i = 0; i < 8; i++) {
                float4 f = *(const float4*)(ks + i * 4);
                hbuf[2 * i]     = __floats2half2_rn(f.x, f.y);
                hbuf[2 * i + 1] = __floats2half2_rn(f.z, f.w);
            }
#pragma unroll
            for (int i = 0; i < 4; i++)
                *(uint4*)&Ks[r][c0 + i * 8] = *(uint4*)&hbuf[i * 4];
#pragma unroll
            for (int i = 0; i < 8; i++) {
                float4 f = *(const float4*)(vs + i * 4);
                hbuf[2 * i]     = __floats2half2_rn(f.x, f.y);
                hbuf[2 * i + 1] = __floats2half2_rn(f.z, f.w);
            }
#pragma unroll
            for (int i = 0; i < 4; i++)
                *(uint4*)&Vs[r][c0 + i * 8] = *(uint4*)&hbuf[i * 4];
        }
        if (tid < 64) {
            float p = padm[rowbase + k0 + tid];
            padS[tid] = (p > 0.f) ? -1e30f : 0.f;
        }
        __syncthreads();

        // ---- S = Q @ K^T (16 rows x 64 keys per warp) ----
        float sacc[8][4];
#pragma unroll
        for (int nt = 0; nt < 8; nt++)
#pragma unroll
            for (int i = 0; i < 4; i++) sacc[nt][i] = 0.f;

#pragma unroll
        for (int kc = 0; kc < 4; kc++) {
            uint32_t kb[4][4];
#pragma unroll
            for (int g = 0; g < 4; g++)
                ldmatrix_x4(kb[g][0], kb[g][1], kb[g][2], kb[g][3],
                            smem_u32(&Ks[g * 16 + brow][bcol]) + kc * 32);
#pragma unroll
            for (int nt = 0; nt < 8; nt++) {
                const int g = nt >> 1, hh = (nt & 1) * 2;
                mma_16816(sacc[nt], aq[kc], kb[g][hh], kb[g][hh + 1]);
            }
        }

        // ---- mask + scale; per-row max over quad ----
        const bool diag = (kt == qt);
        float mx0 = -1e30f, mx1 = -1e30f;
#pragma unroll
        for (int nt = 0; nt < 8; nt++) {
            const int colb = nt * 8 + (l & 3) * 2;
            const float pad0 = padS[colb], pad1 = padS[colb + 1];
            float v0 = sacc[nt][0] * 0.125f + pad0;
            float v1 = sacc[nt][1] * 0.125f + pad1;
            float v2 = sacc[nt][2] * 0.125f + pad0;
            float v3 = sacc[nt][3] * 0.125f + pad1;
            if (diag) {
                const int kg0 = k0 + colb, kg1 = kg0 + 1;
                if (kg0 > qlo) v0 = -1e30f;
                if (kg1 > qlo) v1 = -1e30f;
                if (kg0 > qhi) v2 = -1e30f;
                if (kg1 > qhi) v3 = -1e30f;
            }
            sacc[nt][0] = v0; sacc[nt][1] = v1;
            sacc[nt][2] = v2; sacc[nt][3] = v3;
            mx0 = fmaxf(mx0, fmaxf(v0, v1));
            mx1 = fmaxf(mx1, fmaxf(v2, v3));
        }
        mx0 = fmaxf(mx0, __shfl_xor_sync(0xFFFFFFFF, mx0, 1));
        mx0 = fmaxf(mx0, __shfl_xor_sync(0xFFFFFFFF, mx0, 2));
        mx1 = fmaxf(mx1, __shfl_xor_sync(0xFFFFFFFF, mx1, 1));
        mx1 = fmaxf(mx1, __shfl_xor_sync(0xFFFFFFFF, mx1, 2));

        const float mn0 = fmaxf(m_r[0], mx0);
        const float mn1 = fmaxf(m_r[1], mx1);
        const float al0 = __expf(m_r[0] - mn0);
        const float al1 = __expf(m_r[1] - mn1);
        m_r[0] = mn0; m_r[1] = mn1;

        float sum0 = 0.f, sum1 = 0.f;
#pragma unroll
        for (int nt = 0; nt < 8; nt++) {
            float p0 = __expf(sacc[nt][0] - mn0);
            float p1 = __expf(sacc[nt][1] - mn0);
            float p2 = __expf(sacc[nt][2] - mn1);
            float p3 = __expf(sacc[nt][3] - mn1);
            sacc[nt][0] = p0; sacc[nt][1] = p1;
            sacc[nt][2] = p2; sacc[nt][3] = p3;
            sum0 += p0 + p1;
            sum1 += p2 + p3;
        }
        sum0 += __shfl_xor_sync(0xFFFFFFFF, sum0, 1);
        sum0 += __shfl_xor_sync(0xFFFFFFFF, sum0, 2);
        sum1 += __shfl_xor_sync(0xFFFFFFFF, sum1, 1);
        sum1 += __shfl_xor_sync(0xFFFFFFFF, sum1, 2);
        l_r[0] = l_r[0] * al0 + sum0;
        l_r[1] = l_r[1] * al1 + sum1;

        // ---- rescale O ----
#pragma unroll
        for (int nt = 0; nt < 8; nt++) {
            oacc[nt][0] *= al0; oacc[nt][1] *= al0;
            oacc[nt][2] *= al1; oacc[nt][3] *= al1;
        }

        // ---- O += P @ V ----
#pragma unroll
        for (int kc = 0; kc < 4; kc++) {
            // P fragment for keys kc*16..+15 (accumulator -> A fragment)
            uint32_t pa[4];
            __half2 t0 = __floats2half2_rn(sacc[2 * kc][0],     sacc[2 * kc][1]);
            __half2 t1 = __floats2half2_rn(sacc[2 * kc][2],     sacc[2 * kc][3]);
            __half2 t2 = __floats2half2_rn(sacc[2 * kc + 1][0], sacc[2 * kc + 1][1]);
            __half2 t3 = __floats2half2_rn(sacc[2 * kc + 1][2], sacc[2 * kc + 1][3]);
            pa[0] = reinterpret_cast<uint32_t&>(t0);
            pa[1] = reinterpret_cast<uint32_t&>(t1);
            pa[2] = reinterpret_cast<uint32_t&>(t2);
            pa[3] = reinterpret_cast<uint32_t&>(t3);

            uint32_t vb[4][4];
#pragma unroll
            for (int g = 0; g < 4; g++)
                ldmatrix_x4_trans(vb[g][0], vb[g][1], vb[g][2], vb[g][3],
                                  smem_u32(&Vs[kc * 16 + frow][g * 16 + fcol]));
#pragma unroll
            for (int nt = 0; nt < 8; nt++) {
                const int g = nt >> 1, hh = (nt & 1) * 2;
                mma_16816(oacc[nt], pa, vb[g][hh], vb[g][hh + 1]);
            }
        }
    }

    // ---- epilogue: normalize, store fp32 ----
    const float inv0 = 1.f / l_r[0];
    const float inv1 = 1.f / l_r[1];
    const size_t row_lo = rowbase + q0 + w * 16 + (l >> 2);
    const size_t row_hi = row_lo + 8;
#pragma unroll
    for (int nt = 0; nt < 8; nt++) {
        const int col = colq + nt * 8 + (l & 3) * 2;
        float2 o0, o1;
        o0.x = oacc[nt][0] * inv0; o0.y = oacc[nt][1] * inv0;
        o1.x = oacc[nt][2] * inv1; o1.y = oacc[nt][3] * inv1;
        *(float2*)(Og + row_lo * DMODEL + col) = o0;
        *(float2*)(Og + row_hi * DMODEL + col) = o1;
    }
}

// ---------------------------------------------------------------------------
extern "C" void kernel_launch(void* const* d_in, const int* in_sizes, int n_in,
                              void* d_out, int out_size)
{
    const float* input = (const float*)d_in[0];
    const float* padm  = (const float*)d_in[1];
    const float* wq_w  = (const float*)d_in[2];
    const float* wq_b  = (const float*)d_in[3];
    const float* wk_w  = (const float*)d_in[4];
    const float* wk_b  = (const float*)d_in[5];
    const float* wv_w  = (const float*)d_in[6];
    const float* wv_b  = (const float*)d_in[7];
    const float* fin_w = (const float*)d_in[8];
    const float* fin_b = (const float*)d_in[9];
    float* out = (float*)d_out;

    float *Qp, *Kp, *Vp, *Ap;
    cudaGetSymbolAddress((void**)&Qp, g_Q);
    cudaGetSymbolAddress((void**)&Kp, g_K);
    cudaGetSymbolAddress((void**)&Vp, g_V);
    cudaGetSymbolAddress((void**)&Ap, g_A);

    dim3 gemm_grid(DMODEL / 128, NROWS / 128);  // (8, 32)

    // QKV projections (fp16 mma.sync tensor-core)
    hgemm_mma_kernel<<<gemm_grid, 256>>>(input, wq_w, wq_b, Qp, NROWS, DMODEL, DMODEL);
    hgemm_mma_kernel<<<gemm_grid, 256>>>(input, wk_w, wk_b, Kp, NROWS, DMODEL, DMODEL);
    hgemm_mma_kernel<<<gemm_grid, 256>>>(input, wv_w, wv_b, Vp, NROWS, DMODEL, DMODEL);

    // Causal attention (fp16 tensor-core flash)
    dim3 attn_grid(SLEN / 64, NHEAD, BATCH);   // (32, 16, 2)
    flash_attn_mma_kernel<<<attn_grid, 128>>>(Qp, Kp, Vp, padm, Ap);

    // Output projection (fp16 mma.sync tensor-core)
    hgemm_mma_kernel<<<gemm_grid, 256>>>(Ap, fin_w, fin_b, out, NROWS, DMODEL, DMODEL);
}

// round 10
// speedup vs baseline: 4.9285x; 1.4191x over previous
#include <cuda_runtime.h>
#include <cuda_fp16.h>
#include <cuda_bf16.h>
#include <math.h>
#include <stdint.h>

// Problem constants
#define BATCH 2
#define SLEN  2048
#define DMODEL 1024
#define NHEAD 16
#define HDIM  64          // DK == DV
#define NROWS (BATCH*SLEN)        // 4096

// scratch buffers (half precision end-to-end; no allocations allowed)
__device__ __half g_Qh[NROWS * DMODEL];
__device__ __half g_Kh[NROWS * DMODEL];
__device__ __half g_Vh[NROWS * DMODEL];
__device__ __half g_Ah[NROWS * DMODEL];   // attention output [b,s,h*dv]

__device__ __forceinline__ uint32_t smem_u32(const void* p) {
    uint32_t a;
    asm("{ .reg .u64 t; cvta.to.shared.u64 t, %1; cvt.u32.u64 %0, t; }"
        : "=r"(a) : "l"(p));
    return a;
}

__device__ __forceinline__ void ldmatrix_x4(uint32_t& r0, uint32_t& r1,
                                            uint32_t& r2, uint32_t& r3,
                                            uint32_t addr) {
    asm volatile("ldmatrix.sync.aligned.m8n8.x4.shared.b16 {%0,%1,%2,%3}, [%4];"
                 : "=r"(r0), "=r"(r1), "=r"(r2), "=r"(r3) : "r"(addr));
}

__device__ __forceinline__ void ldmatrix_x4_trans(uint32_t& r0, uint32_t& r1,
                                                  uint32_t& r2, uint32_t& r3,
                                                  uint32_t addr) {
    asm volatile("ldmatrix.sync.aligned.m8n8.x4.trans.shared.b16 {%0,%1,%2,%3}, [%4];"
                 : "=r"(r0), "=r"(r1), "=r"(r2), "=r"(r3) : "r"(addr));
}

__device__ __forceinline__ void mma_16816(float* d, const uint32_t* a,
                                          uint32_t b0, uint32_t b1) {
    asm volatile(
        "mma.sync.aligned.m16n8k16.row.col.f32.f16.f16.f32 "
        "{%0,%1,%2,%3}, {%4,%5,%6,%7}, {%8,%9}, {%0,%1,%2,%3};"
        : "+f"(d[0]), "+f"(d[1]), "+f"(d[2]), "+f"(d[3])
        : "r"(a[0]), "r"(a[1]), "r"(a[2]), "r"(a[3]), "r"(b0), "r"(b1));
}

__device__ __forceinline__ void cp_async16(uint32_t dst, const void* src) {
    asm volatile("cp.async.cg.shared.global [%0], [%1], 16;"
                 :: "r"(dst), "l"(src));
}
__device__ __forceinline__ void cp_async_commit() {
    asm volatile("cp.async.commit_group;");
}
__device__ __forceinline__ void cp_async_wait0() {
    asm volatile("cp.async.wait_group 0;");
}

// ---- staging/output overloads (pick float or half path at compile time) ----
// stage 16 elements of A row into smem as halves
__device__ __forceinline__ void stage16(const float* src, __half* dst) {
    float4 f0 = *(const float4*)(src + 0);
    float4 f1 = *(const float4*)(src + 4);
    float4 f2 = *(const float4*)(src + 8);
    float4 f3 = *(const float4*)(src + 12);
    __half2 h[8];
    h[0] = __floats2half2_rn(f0.x, f0.y); h[1] = __floats2half2_rn(f0.z, f0.w);
    h[2] = __floats2half2_rn(f1.x, f1.y); h[3] = __floats2half2_rn(f1.z, f1.w);
    h[4] = __floats2half2_rn(f2.x, f2.y); h[5] = __floats2half2_rn(f2.z, f2.w);
    h[6] = __floats2half2_rn(f3.x, f3.y); h[7] = __floats2half2_rn(f3.z, f3.w);
    *(uint4*)(dst + 0) = *(uint4*)&h[0];
    *(uint4*)(dst + 8) = *(uint4*)&h[4];
}
__device__ __forceinline__ void stage16(const __half* src, __half* dst) {
    *(uint4*)(dst + 0) = *(const uint4*)(src + 0);
    *(uint4*)(dst + 8) = *(const uint4*)(src + 8);
}
// store pair (a,b) at C[idx], C[idx+1]
__device__ __forceinline__ void store2(float* C, size_t idx, float a, float b) {
    float2 o; o.x = a; o.y = b;
    *(float2*)(C + idx) = o;
}
__device__ __forceinline__ void store2(__half* C, size_t idx, float a, float b) {
    *(__half2*)(C + idx) = __floats2half2_rn(a, b);
}

// ===========================================================================
// HGEMM via mma.sync (f16 compute, fp32 accum): C[M,N] = A[M,K] @ W[N,K]^T + b
// TIN: float or __half (A matrix); TOUT: float or __half (C matrix).
// CTA 128x128, 256 threads (2x4 warps, 64x32/warp), BK=32. (verified R7)
// ===========================================================================
#define BKK 32
#define KPAD 40   // 80B row stride

template<typename TIN, typename TOUT>
__global__ __launch_bounds__(256) void hgemm_mma_kernel(
    const TIN* __restrict__ A, const float* __restrict__ W,
    const float* __restrict__ bias, TOUT* __restrict__ C,
    int M, int N, int K)
{
    __shared__ __half As[128][KPAD];
    __shared__ __half Ws[128][KPAD];

    const int tid = threadIdx.x;
    const int wid = tid >> 5;
    const int l   = tid & 31;
    const int bn = blockIdx.x * 128;
    const int bm = blockIdx.y * 128;

    const int wm = wid & 1;
    const int wn = wid >> 1;
    const int m_base = wm * 64;
    const int n_base = wn * 32;

    const int sr = tid >> 1;
    const int sk = (tid & 1) * 16;

    const int arow = m_base + (l & 7) + 8 * ((l >> 3) & 1);
    const int acol = (l >> 4) * 8;
    uint32_t a_addr[4];
#pragma unroll
    for (int mt = 0; mt < 4; mt++)
        a_addr[mt] = smem_u32(&As[arow + mt * 16][acol]);

    const int brow = n_base + (l & 7) + 8 * (l >> 4);
    const int bcol = ((l >> 3) & 1) * 8;
    uint32_t b_addr[2];
#pragma unroll
    for (int np = 0; np < 2; np++)
        b_addr[np] = smem_u32(&Ws[brow + np * 16][bcol]);

    float acc[4][4][4];
#pragma unroll
    for (int mt = 0; mt < 4; mt++)
#pragma unroll
        for (int nt = 0; nt < 4; nt++)
#pragma unroll
            for (int i = 0; i < 4; i++) acc[mt][nt][i] = 0.f;

    const TIN*   Ap = A + (size_t)(bm + sr) * K + sk;
    const float* Wp = W + (size_t)(bn + sr) * K + sk;

    for (int k0 = 0; k0 < K; k0 += BKK) {
        stage16(Ap + k0, &As[sr][sk]);
        stage16(Wp + k0, &Ws[sr][sk]);
        __syncthreads();

#pragma unroll
        for (int ks = 0; ks < 2; ks++) {
            const uint32_t koff = ks * 32;
            uint32_t af[4][4];
#pragma unroll
            for (int mt = 0; mt < 4; mt++)
                ldmatrix_x4(af[mt][0], af[mt][1], af[mt][2], af[mt][3],
                            a_addr[mt] + koff);
            uint32_t bf[2][4];
#pragma unroll
            for (int np = 0; np < 2; np++)
                ldmatrix_x4(bf[np][0], bf[np][1], bf[np][2], bf[np][3],
                            b_addr[np] + koff);
#pragma unroll
            for (int mt = 0; mt < 4; mt++)
#pragma unroll
                for (int nt = 0; nt < 4; nt++) {
                    const int np = nt >> 1, hh = (nt & 1) * 2;
                    mma_16816(acc[mt][nt], af[mt], bf[np][hh], bf[np][hh + 1]);
                }
        }
        __syncthreads();
    }

    const int rl = l >> 2;
    const int cl = (l & 3) * 2;
#pragma unroll
    for (int mt = 0; mt < 4; mt++) {
#pragma unroll
        for (int nt = 0; nt < 4; nt++) {
            const int row = bm + m_base + mt * 16 + rl;
            const int col = bn + n_base + nt * 8 + cl;
            const float b0 = bias[col], b1 = bias[col + 1];
            store2(C, (size_t)row * N + col,
                   acc[mt][nt][0] + b0, acc[mt][nt][1] + b1);
            store2(C, (size_t)(row + 8) * N + col,
                   acc[mt][nt][2] + b0, acc[mt][nt][3] + b1);
        }
    }
}

// ===========================================================================
// Tensor-core flash attention, fp16 I/O, double-buffered cp.async K/V.
// CTA: 64 queries of one (b,h); 128 threads; warp w owns rows w*16..+15.
// Key tiles of 64; online softmax in registers (verified R8 layout).
// ===========================================================================
#define FPAD 72   // 144B row stride (conflict-free ldmatrix)

__global__ __launch_bounds__(128) void flash_attn_mma_kernel(
    const __half* __restrict__ Qg, const __half* __restrict__ Kg,
    const __half* __restrict__ Vg, const float* __restrict__ padm,
    __half* __restrict__ Og)
{
    __shared__ __half Qs[64][FPAD];
    __shared__ __half Ks[2][64][FPAD];
    __shared__ __half Vs[2][64][FPAD];
    __shared__ float padS[2][64];

    const int tid = threadIdx.x;
    const int w = tid >> 5;
    const int l = tid & 31;
    const int qt = blockIdx.x, h = blockIdx.y, b = blockIdx.z;
    const int q0 = qt * 64;
    const size_t rowbase = (size_t)b * SLEN;
    const int colq = h * HDIM;

    // ---- stage Q tile (64x64 half, straight copies) ----
    {
        const int r = tid >> 1, c0 = (tid & 1) * 32;
        const __half* src = Qg + (rowbase + q0 + r) * DMODEL + colq + c0;
#pragma unroll
        for (int i = 0; i < 4; i++)
            *(uint4*)&Qs[r][c0 + i * 8] = *(const uint4*)(src + i * 8);
    }

    const int nkt = qt + 1;

    // ---- prefetch K/V tile 0 into buffer 0 ----
    {
        const int k0 = 0;
#pragma unroll
        for (int i = 0; i < 4; i++) {
            const int idx = tid + i * 128;          // 0..511
            const int r = idx >> 3, c = (idx & 7) * 8;
            const size_t gro = (rowbase + k0 + r) * DMODEL + colq + c;
            cp_async16(smem_u32(&Ks[0][r][c]), Kg + gro);
            cp_async16(smem_u32(&Vs[0][r][c]), Vg + gro);
        }
        cp_async_commit();
        if (tid < 64) {
            float p = padm[rowbase + k0 + tid];
            padS[0][tid] = (p > 0.f) ? -1e30f : 0.f;
        }
    }
    __syncthreads();   // Qs visible

    // fragment lane addresses
    const int frow = (l & 7) + 8 * ((l >> 3) & 1);   // A & V-trans row pattern
    const int fcol = (l >> 4) * 8;
    const uint32_t q_addr = smem_u32(&Qs[w * 16 + frow][fcol]);
    const int brow = (l & 7) + 8 * (l >> 4);          // K (non-trans B) pattern
    const int bcol = ((l >> 3) & 1) * 8;

    // Q fragments (loop-invariant)
    uint32_t aq[4][4];
#pragma unroll
    for (int kc = 0; kc < 4; kc++)
        ldmatrix_x4(aq[kc][0], aq[kc][1], aq[kc][2], aq[kc][3],
                    q_addr + kc * 32);

    float oacc[8][4];
#pragma unroll
    for (int nt = 0; nt < 8; nt++)
#pragma unroll
        for (int i = 0; i < 4; i++) oacc[nt][i] = 0.f;
    float m_r[2] = {-1e30f, -1e30f};
    float l_r[2] = {0.f, 0.f};

    const int qlo = q0 + w * 16 + (l >> 2);
    const int qhi = qlo + 8;

    for (int kt = 0; kt < nkt; kt++) {
        const int k0 = kt * 64;
        const int cur = kt & 1;

        cp_async_wait0();
        __syncthreads();   // K/V[cur] + padS[cur] visible; prev compute done

        // ---- prefetch next tile into the other buffer ----
        if (kt + 1 < nkt) {
            const int kn = k0 + 64;
            const int nb = cur ^ 1;
#pragma unroll
            for (int i = 0; i < 4; i++) {
                const int idx = tid + i * 128;
                const int r = idx >> 3, c = (idx & 7) * 8;
                const size_t gro = (rowbase + kn + r) * DMODEL + colq + c;
                cp_async16(smem_u32(&Ks[nb][r][c]), Kg + gro);
                cp_async16(smem_u32(&Vs[nb][r][c]), Vg + gro);
            }
            cp_async_commit();
            if (tid < 64) {
                float p = padm[rowbase + kn + tid];
                padS[nb][tid] = (p > 0.f) ? -1e30f : 0.f;
            }
        }

        // ---- S = Q @ K^T (16 rows x 64 keys per warp) ----
        float sacc[8][4];
#pragma unroll
        for (int nt = 0; nt < 8; nt++)
#pragma unroll
            for (int i = 0; i < 4; i++) sacc[nt][i] = 0.f;

#pragma unroll
        for (int kc = 0; kc < 4; kc++) {
            uint32_t kb[4][4];
#pragma unroll
            for (int g = 0; g < 4; g++)
                ldmatrix_x4(kb[g][0], kb[g][1], kb[g][2], kb[g][3],
                            smem_u32(&Ks[cur][g * 16 + brow][bcol]) + kc * 32);
#pragma unroll
            for (int nt = 0; nt < 8; nt++) {
                const int g = nt >> 1, hh = (nt & 1) * 2;
                mma_16816(sacc[nt], aq[kc], kb[g][hh], kb[g][hh + 1]);
            }
        }

        // ---- mask + scale; per-row max over quad ----
        const bool diag = (kt == qt);
        float mx0 = -1e30f, mx1 = -1e30f;
#pragma unroll
        for (int nt = 0; nt < 8; nt++) {
            const int colb = nt * 8 + (l & 3) * 2;
            const float pad0 = padS[cur][colb], pad1 = padS[cur][colb + 1];
            float v0 = sacc[nt][0] * 0.125f + pad0;
            float v1 = sacc[nt][1] * 0.125f + pad1;
            float v2 = sacc[nt][2] * 0.125f + pad0;
            float v3 = sacc[nt][3] * 0.125f + pad1;
            if (diag) {
                const int kg0 = k0 + colb, kg1 = kg0 + 1;
                if (kg0 > qlo) v0 = -1e30f;
                if (kg1 > qlo) v1 = -1e30f;
                if (kg0 > qhi) v2 = -1e30f;
                if (kg1 > qhi) v3 = -1e30f;
            }
            sacc[nt][0] = v0; sacc[nt][1] = v1;
            sacc[nt][2] = v2; sacc[nt][3] = v3;
            mx0 = fmaxf(mx0, fmaxf(v0, v1));
            mx1 = fmaxf(mx1, fmaxf(v2, v3));
        }
        mx0 = fmaxf(mx0, __shfl_xor_sync(0xFFFFFFFF, mx0, 1));
        mx0 = fmaxf(mx0, __shfl_xor_sync(0xFFFFFFFF, mx0, 2));
        mx1 = fmaxf(mx1, __shfl_xor_sync(0xFFFFFFFF, mx1, 1));
        mx1 = fmaxf(mx1, __shfl_xor_sync(0xFFFFFFFF, mx1, 2));

        const float mn0 = fmaxf(m_r[0], mx0);
        const float mn1 = fmaxf(m_r[1], mx1);
        const float al0 = __expf(m_r[0] - mn0);
        const float al1 = __expf(m_r[1] - mn1);
        m_r[0] = mn0; m_r[1] = mn1;

        float sum0 = 0.f, sum1 = 0.f;
#pragma unroll
        for (int nt = 0; nt < 8; nt++) {
            float p0 = __expf(sacc[nt][0] - mn0);
            float p1 = __expf(sacc[nt][1] - mn0);
            float p2 = __expf(sacc[nt][2] - mn1);
            float p3 = __expf(sacc[nt][3] - mn1);
            sacc[nt][0] = p0; sacc[nt][1] = p1;
            sacc[nt][2] = p2; sacc[nt][3] = p3;
            sum0 += p0 + p1;
            sum1 += p2 + p3;
        }
        sum0 += __shfl_xor_sync(0xFFFFFFFF, sum0, 1);
        sum0 += __shfl_xor_sync(0xFFFFFFFF, sum0, 2);
        sum1 += __shfl_xor_sync(0xFFFFFFFF, sum1, 1);
        sum1 += __shfl_xor_sync(0xFFFFFFFF, sum1, 2);
        l_r[0] = l_r[0] * al0 + sum0;
        l_r[1] = l_r[1] * al1 + sum1;

        // ---- rescale O ----
#pragma unroll
        for (int nt = 0; nt < 8; nt++) {
            oacc[nt][0] *= al0; oacc[nt][1] *= al0;
            oacc[nt][2] *= al1; oacc[nt][3] *= al1;
        }

        // ---- O += P @ V ----
#pragma unroll
        for (int kc = 0; kc < 4; kc++) {
            uint32_t pa[4];
            __half2 t0 = __floats2half2_rn(sacc[2 * kc][0],     sacc[2 * kc][1]);
            __half2 t1 = __floats2half2_rn(sacc[2 * kc][2],     sacc[2 * kc][3]);
            __half2 t2 = __floats2half2_rn(sacc[2 * kc + 1][0], sacc[2 * kc + 1][1]);
            __half2 t3 = __floats2half2_rn(sacc[2 * kc + 1][2], sacc[2 * kc + 1][3]);
            pa[0] = reinterpret_cast<uint32_t&>(t0);
            pa[1] = reinterpret_cast<uint32_t&>(t1);
            pa[2] = reinterpret_cast<uint32_t&>(t2);
            pa[3] = reinterpret_cast<uint32_t&>(t3);

            uint32_t vb[4][4];
#pragma unroll
            for (int g = 0; g < 4; g++)
                ldmatrix_x4_trans(vb[g][0], vb[g][1], vb[g][2], vb[g][3],
                                  smem_u32(&Vs[cur][kc * 16 + frow][g * 16 + fcol]));
#pragma unroll
            for (int nt = 0; nt < 8; nt++) {
                const int g = nt >> 1, hh = (nt & 1) * 2;
                mma_16816(oacc[nt], pa, vb[g][hh], vb[g][hh + 1]);
            }
        }
    }

    // ---- epilogue: normalize, store half ----
    const float inv0 = 1.f / l_r[0];
    const float inv1 = 1.f / l_r[1];
    const size_t row_lo = rowbase + q0 + w * 16 + (l >> 2);
    const size_t row_hi = row_lo + 8;
#pragma unroll
    for (int nt = 0; nt < 8; nt++) {
        const int col = colq + nt * 8 + (l & 3) * 2;
        *(__half2*)(Og + row_lo * DMODEL + col) =
            __floats2half2_rn(oacc[nt][0] * inv0, oacc[nt][1] * inv0);
        *(__half2*)(Og + row_hi * DMODEL + col) =
            __floats2half2_rn(oacc[nt][2] * inv1, oacc[nt][3] * inv1);
    }
}

// ---------------------------------------------------------------------------
extern "C" void kernel_launch(void* const* d_in, const int* in_sizes, int n_in,
                              void* d_out, int out_size)
{
    const float* input = (const float*)d_in[0];
    const float* padm  = (const float*)d_in[1];
    const float* wq_w  = (const float*)d_in[2];
    const float* wq_b  = (const float*)d_in[3];
    const float* wk_w  = (const float*)d_in[4];
    const float* wk_b  = (const float*)d_in[5];
    const float* wv_w  = (const float*)d_in[6];
    const float* wv_b  = (const float*)d_in[7];
    const float* fin_w = (const float*)d_in[8];
    const float* fin_b = (const float*)d_in[9];
    float* out = (float*)d_out;

    __half *Qp, *Kp, *Vp, *Ap;
    cudaGetSymbolAddress((void**)&Qp, g_Qh);
    cudaGetSymbolAddress((void**)&Kp, g_Kh);
    cudaGetSymbolAddress((void**)&Vp, g_Vh);
    cudaGetSymbolAddress((void**)&Ap, g_Ah);

    dim3 gemm_grid(DMODEL / 128, NROWS / 128);  // (8, 32)

    // QKV projections (f16 mma.sync, half outputs)
    hgemm_mma_kernel<float, __half><<<gemm_grid, 256>>>(input, wq_w, wq_b, Qp, NROWS, DMODEL, DMODEL);
    hgemm_mma_kernel<float, __half><<<gemm_grid, 256>>>(input, wk_w, wk_b, Kp, NROWS, DMODEL, DMODEL);
    hgemm_mma_kernel<float, __half><<<gemm_grid, 256>>>(input, wv_w, wv_b, Vp, NROWS, DMODEL, DMODEL);

    // Causal attention (f16 tensor-core flash, cp.async double-buffered)
    dim3 attn_grid(SLEN / 64, NHEAD, BATCH);   // (32, 16, 2)
    flash_attn_mma_kernel<<<attn_grid, 128>>>(Qp, Kp, Vp, padm, Ap);

    // Output projection (half input, float output)
    hgemm_mma_kernel<__half, float><<<gemm_grid, 256>>>(Ap, fin_w, fin_b, out, NROWS, DMODEL, DMODEL);
}

// round 13
// speedup vs baseline: 6.8163x; 1.3830x over previous
#include <cuda_runtime.h>
#include <cuda_fp16.h>
#include <cuda_bf16.h>
#include <math.h>
#include <stdint.h>

// Problem constants
#define BATCH 2
#define SLEN  2048
#define DMODEL 1024
#define NHEAD 16
#define HDIM  64          // DK == DV
#define NROWS (BATCH*SLEN)        // 4096

// scratch buffers (half precision end-to-end; no allocations allowed)
__device__ __half g_Qh[NROWS * DMODEL];
__device__ __half g_Kh[NROWS * DMODEL];
__device__ __half g_Vh[NROWS * DMODEL];
__device__ __half g_Ah[NROWS * DMODEL];     // attention output [b,s,h*dv]
__device__ __half g_Xh[NROWS * DMODEL];     // input converted to f16
__device__ __half g_Wqh[DMODEL * DMODEL];   // weights converted to f16
__device__ __half g_Wkh[DMODEL * DMODEL];
__device__ __half g_Wvh[DMODEL * DMODEL];
__device__ __half g_Wfh[DMODEL * DMODEL];

__device__ __forceinline__ uint32_t smem_u32(const void* p) {
    uint32_t a;
    asm("{ .reg .u64 t; cvta.to.shared.u64 t, %1; cvt.u32.u64 %0, t; }"
        : "=r"(a) : "l"(p));
    return a;
}

__device__ __forceinline__ void ldmatrix_x4(uint32_t& r0, uint32_t& r1,
                                            uint32_t& r2, uint32_t& r3,
                                            uint32_t addr) {
    asm volatile("ldmatrix.sync.aligned.m8n8.x4.shared.b16 {%0,%1,%2,%3}, [%4];"
                 : "=r"(r0), "=r"(r1), "=r"(r2), "=r"(r3) : "r"(addr));
}

__device__ __forceinline__ void ldmatrix_x4_trans(uint32_t& r0, uint32_t& r1,
                                                  uint32_t& r2, uint32_t& r3,
                                                  uint32_t addr) {
    asm volatile("ldmatrix.sync.aligned.m8n8.x4.trans.shared.b16 {%0,%1,%2,%3}, [%4];"
                 : "=r"(r0), "=r"(r1), "=r"(r2), "=r"(r3) : "r"(addr));
}

__device__ __forceinline__ void mma_16816(float* d, const uint32_t* a,
                                          uint32_t b0, uint32_t b1) {
    asm volatile(
        "mma.sync.aligned.m16n8k16.row.col.f32.f16.f16.f32 "
        "{%0,%1,%2,%3}, {%4,%5,%6,%7}, {%8,%9}, {%0,%1,%2,%3};"
        : "+f"(d[0]), "+f"(d[1]), "+f"(d[2]), "+f"(d[3])
        : "r"(a[0]), "r"(a[1]), "r"(a[2]), "r"(a[3]), "r"(b0), "r"(b1));
}

__device__ __forceinline__ void cp_async16(uint32_t dst, const void* src) {
    asm volatile("cp.async.cg.shared.global [%0], [%1], 16;"
                 :: "r"(dst), "l"(src));
}
__device__ __forceinline__ void cp_async_commit() {
    asm volatile("cp.async.commit_group;");
}
__device__ __forceinline__ void cp_async_wait0() {
    asm volatile("cp.async.wait_group 0;");
}

// store pair (a,b) at C[idx], C[idx+1]
__device__ __forceinline__ void store2(float* C, size_t idx, float a, float b) {
    float2 o; o.x = a; o.y = b;
    *(float2*)(C + idx) = o;
}
__device__ __forceinline__ void store2(__half* C, size_t idx, float a, float b) {
    *(__half2*)(C + idx) = __floats2half2_rn(a, b);
}

// ===========================================================================
// fp32 -> f16 streaming convert (8 elems/thread)
// ===========================================================================
__global__ __launch_bounds__(256) void cvt_f32_f16_kernel(
    const float* __restrict__ src, __half* __restrict__ dst, int n)
{
    const int i = (blockIdx.x * 256 + threadIdx.x) * 8;
    if (i >= n) return;
    float4 a = *(const float4*)(src + i);
    float4 b = *(const float4*)(src + i + 4);
    __half2 h[4];
    h[0] = __floats2half2_rn(a.x, a.y);
    h[1] = __floats2half2_rn(a.z, a.w);
    h[2] = __floats2half2_rn(b.x, b.y);
    h[3] = __floats2half2_rn(b.z, b.w);
    *(uint4*)(dst + i) = *(uint4*)&h[0];
}

// ===========================================================================
// HGEMM, pure f16 inputs, cp.async double-buffered.
// C[M,N] = A[M,K] @ W[N,K]^T + bias[N]
// CTA 128x128, 256 threads (2x4 warps, 64x32/warp), BK=32, 2 stages.
// Fragment/compute path identical to verified R7 kernel.
// ===========================================================================
#define BKK 32
#define KPAD 40                       // 80B row stride (conflict-free ldmatrix)
#define STAGE_BYTES (128 * KPAD * 2)  // 10240

template<typename TOUT>
__global__ __launch_bounds__(256) void hgemm_db_kernel(
    const __half* __restrict__ A, const __half* __restrict__ W,
    const float* __restrict__ bias, TOUT* __restrict__ C,
    int M, int N, int K)
{
    __shared__ __half As[2][128][KPAD];
    __shared__ __half Ws[2][128][KPAD];

    const int tid = threadIdx.x;
    const int wid = tid >> 5;
    const int l   = tid & 31;
    const int bn = blockIdx.x * 128;
    const int bm = blockIdx.y * 128;

    const int wm = wid & 1;
    const int wn = wid >> 1;
    const int m_base = wm * 64;
    const int n_base = wn * 32;

    // staging chunk map: 512 16B chunks per matrix, 2 per thread per matrix
    const int j0 = tid, j1 = tid + 256;
    const int r0s = j0 >> 2, c0s = (j0 & 3) * 8;
    const int r1s = j1 >> 2, c1s = (j1 & 3) * 8;

    const uint32_t as0 = smem_u32(&As[0][r0s][c0s]);
    const uint32_t as1 = smem_u32(&As[0][r1s][c1s]);
    const uint32_t ws0 = smem_u32(&Ws[0][r0s][c0s]);
    const uint32_t ws1 = smem_u32(&Ws[0][r1s][c1s]);
    const __half* Ap0 = A + (size_t)(bm + r0s) * K + c0s;
    const __half* Ap1 = A + (size_t)(bm + r1s) * K + c1s;
    const __half* Wp0 = W + (size_t)(bn + r0s) * K + c0s;
    const __half* Wp1 = W + (size_t)(bn + r1s) * K + c1s;

    // fragment lane addresses (stage 0 base)
    const int arow = m_base + (l & 7) + 8 * ((l >> 3) & 1);
    const int acol = (l >> 4) * 8;
    uint32_t a_addr[4];
#pragma unroll
    for (int mt = 0; mt < 4; mt++)
        a_addr[mt] = smem_u32(&As[0][arow + mt * 16][acol]);

    const int brow = n_base + (l & 7) + 8 * (l >> 4);
    const int bcol = ((l >> 3) & 1) * 8;
    uint32_t b_addr[2];
#pragma unroll
    for (int np = 0; np < 2; np++)
        b_addr[np] = smem_u32(&Ws[0][brow + np * 16][bcol]);

    float acc[4][4][4];
#pragma unroll
    for (int mt = 0; mt < 4; mt++)
#pragma unroll
        for (int nt = 0; nt < 4; nt++)
#pragma unroll
            for (int i = 0; i < 4; i++) acc[mt][nt][i] = 0.f;

    // prefetch slab 0 into stage 0
    cp_async16(as0, Ap0);
    cp_async16(as1, Ap1);
    cp_async16(ws0, Wp0);
    cp_async16(ws1, Wp1);
    cp_async_commit();

    for (int k0 = 0; k0 < K; k0 += BKK) {
        const int cur = (k0 >> 5) & 1;
        const uint32_t so = cur * STAGE_BYTES;

        cp_async_wait0();
        __syncthreads();

        if (k0 + BKK < K) {
            const uint32_t no = (cur ^ 1) * STAGE_BYTES;
            const int kn = k0 + BKK;
            cp_async16(as0 + no, Ap0 + kn);
            cp_async16(as1 + no, Ap1 + kn);
            cp_async16(ws0 + no, Wp0 + kn);
            cp_async16(ws1 + no, Wp1 + kn);
            cp_async_commit();
        }

#pragma unroll
        for (int ks = 0; ks < 2; ks++) {
            const uint32_t koff = so + ks * 32;
            uint32_t af[4][4];
#pragma unroll
            for (int mt = 0; mt < 4; mt++)
                ldmatrix_x4(af[mt][0], af[mt][1], af[mt][2], af[mt][3],
                            a_addr[mt] + koff);
            uint32_t bf[2][4];
#pragma unroll
            for (int np = 0; np < 2; np++)
                ldmatrix_x4(bf[np][0], bf[np][1], bf[np][2], bf[np][3],
                            b_addr[np] + koff);
#pragma unroll
            for (int mt = 0; mt < 4; mt++)
#pragma unroll
                for (int nt = 0; nt < 4; nt++) {
                    const int np = nt >> 1, hh = (nt & 1) * 2;
                    mma_16816(acc[mt][nt], af[mt], bf[np][hh], bf[np][hh + 1]);
                }
        }
    }

    const int rl = l >> 2;
    const int cl = (l & 3) * 2;
#pragma unroll
    for (int mt = 0; mt < 4; mt++) {
#pragma unroll
        for (int nt = 0; nt < 4; nt++) {
            const int row = bm + m_base + mt * 16 + rl;
            const int col = bn + n_base + nt * 8 + cl;
            const float b0 = bias[col], b1 = bias[col + 1];
            store2(C, (size_t)row * N + col,
                   acc[mt][nt][0] + b0, acc[mt][nt][1] + b1);
            store2(C, (size_t)(row + 8) * N + col,
                   acc[mt][nt][2] + b0, acc[mt][nt][3] + b1);
        }
    }
}

// ===========================================================================
// Tensor-core flash attention, fp16 I/O, double-buffered cp.async K/V.
// (unchanged — verified R10)
// ===========================================================================
#define FPAD 72   // 144B row stride (conflict-free ldmatrix)

__global__ __launch_bounds__(128) void flash_attn_mma_kernel(
    const __half* __restrict__ Qg, const __half* __restrict__ Kg,
    const __half* __restrict__ Vg, const float* __restrict__ padm,
    __half* __restrict__ Og)
{
    __shared__ __half Qs[64][FPAD];
    __shared__ __half Ks[2][64][FPAD];
    __shared__ __half Vs[2][64][FPAD];
    __shared__ float padS[2][64];

    const int tid = threadIdx.x;
    const int w = tid >> 5;
    const int l = tid & 31;
    const int qt = blockIdx.x, h = blockIdx.y, b = blockIdx.z;
    const int q0 = qt * 64;
    const size_t rowbase = (size_t)b * SLEN;
    const int colq = h * HDIM;

    // ---- stage Q tile ----
    {
        const int r = tid >> 1, c0 = (tid & 1) * 32;
        const __half* src = Qg + (rowbase + q0 + r) * DMODEL + colq + c0;
#pragma unroll
        for (int i = 0; i < 4; i++)
            *(uint4*)&Qs[r][c0 + i * 8] = *(const uint4*)(src + i * 8);
    }

    const int nkt = qt + 1;

    // ---- prefetch K/V tile 0 ----
    {
#pragma unroll
        for (int i = 0; i < 4; i++) {
            const int idx = tid + i * 128;
            const int r = idx >> 3, c = (idx & 7) * 8;
            const size_t gro = (rowbase + r) * DMODEL + colq + c;
            cp_async16(smem_u32(&Ks[0][r][c]), Kg + gro);
            cp_async16(smem_u32(&Vs[0][r][c]), Vg + gro);
        }
        cp_async_commit();
        if (tid < 64) {
            float p = padm[rowbase + tid];
            padS[0][tid] = (p > 0.f) ? -1e30f : 0.f;
        }
    }
    __syncthreads();

    const int frow = (l & 7) + 8 * ((l >> 3) & 1);
    const int fcol = (l >> 4) * 8;
    const uint32_t q_addr = smem_u32(&Qs[w * 16 + frow][fcol]);
    const int brow = (l & 7) + 8 * (l >> 4);
    const int bcol = ((l >> 3) & 1) * 8;

    uint32_t aq[4][4];
#pragma unroll
    for (int kc = 0; kc < 4; kc++)
        ldmatrix_x4(aq[kc][0], aq[kc][1], aq[kc][2], aq[kc][3],
                    q_addr + kc * 32);

    float oacc[8][4];
#pragma unroll
    for (int nt = 0; nt < 8; nt++)
#pragma unroll
        for (int i = 0; i < 4; i++) oacc[nt][i] = 0.f;
    float m_r[2] = {-1e30f, -1e30f};
    float l_r[2] = {0.f, 0.f};

    const int qlo = q0 + w * 16 + (l >> 2);
    const int qhi = qlo + 8;

    for (int kt = 0; kt < nkt; kt++) {
        const int k0 = kt * 64;
        const int cur = kt & 1;

        cp_async_wait0();
        __syncthreads();

        if (kt + 1 < nkt) {
            const int kn = k0 + 64;
            const int nb = cur ^ 1;
#pragma unroll
            for (int i = 0; i < 4; i++) {
                const int idx = tid + i * 128;
                const int r = idx >> 3, c = (idx & 7) * 8;
                const size_t gro = (rowbase + kn + r) * DMODEL + colq + c;
                cp_async16(smem_u32(&Ks[nb][r][c]), Kg + gro);
                cp_async16(smem_u32(&Vs[nb][r][c]), Vg + gro);
            }
            cp_async_commit();
            if (tid < 64) {
                float p = padm[rowbase + kn + tid];
                padS[nb][tid] = (p > 0.f) ? -1e30f : 0.f;
            }
        }

        float sacc[8][4];
#pragma unroll
        for (int nt = 0; nt < 8; nt++)
#pragma unroll
            for (int i = 0; i < 4; i++) sacc[nt][i] = 0.f;

#pragma unroll
        for (int kc = 0; kc < 4; kc++) {
            uint32_t kb[4][4];
#pragma unroll
            for (int g = 0; g < 4; g++)
                ldmatrix_x4(kb[g][0], kb[g][1], kb[g][2], kb[g][3],
                            smem_u32(&Ks[cur][g * 16 + brow][bcol]) + kc * 32);
#pragma unroll
            for (int nt = 0; nt < 8; nt++) {
                const int g = nt >> 1, hh = (nt & 1) * 2;
                mma_16816(sacc[nt], aq[kc], kb[g][hh], kb[g][hh + 1]);
            }
        }

        const bool diag = (kt == qt);
        float mx0 = -1e30f, mx1 = -1e30f;
#pragma unroll
        for (int nt = 0; nt < 8; nt++) {
            const int colb = nt * 8 + (l & 3) * 2;
            const float pad0 = padS[cur][colb], pad1 = padS[cur][colb + 1];
            float v0 = sacc[nt][0] * 0.125f + pad0;
            float v1 = sacc[nt][1] * 0.125f + pad1;
            float v2 = sacc[nt][2] * 0.125f + pad0;
            float v3 = sacc[nt][3] * 0.125f + pad1;
            if (diag) {
                const int kg0 = k0 + colb, kg1 = kg0 + 1;
                if (kg0 > qlo) v0 = -1e30f;
                if (kg1 > qlo) v1 = -1e30f;
                if (kg0 > qhi) v2 = -1e30f;
                if (kg1 > qhi) v3 = -1e30f;
            }
            sacc[nt][0] = v0; sacc[nt][1] = v1;
            sacc[nt][2] = v2; sacc[nt][3] = v3;
            mx0 = fmaxf(mx0, fmaxf(v0, v1));
            mx1 = fmaxf(mx1, fmaxf(v2, v3));
        }
        mx0 = fmaxf(mx0, __shfl_xor_sync(0xFFFFFFFF, mx0, 1));
        mx0 = fmaxf(mx0, __shfl_xor_sync(0xFFFFFFFF, mx0, 2));
        mx1 = fmaxf(mx1, __shfl_xor_sync(0xFFFFFFFF, mx1, 1));
        mx1 = fmaxf(mx1, __shfl_xor_sync(0xFFFFFFFF, mx1, 2));

        const float mn0 = fmaxf(m_r[0], mx0);
        const float mn1 = fmaxf(m_r[1], mx1);
        const float al0 = __expf(m_r[0] - mn0);
        const float al1 = __expf(m_r[1] - mn1);
        m_r[0] = mn0; m_r[1] = mn1;

        float sum0 = 0.f, sum1 = 0.f;
#pragma unroll
        for (int nt = 0; nt < 8; nt++) {
            float p0 = __expf(sacc[nt][0] - mn0);
            float p1 = __expf(sacc[nt][1] - mn0);
            float p2 = __expf(sacc[nt][2] - mn1);
            float p3 = __expf(sacc[nt][3] - mn1);
            sacc[nt][0] = p0; sacc[nt][1] = p1;
            sacc[nt][2] = p2; sacc[nt][3] = p3;
            sum0 += p0 + p1;
            sum1 += p2 + p3;
        }
        sum0 += __shfl_xor_sync(0xFFFFFFFF, sum0, 1);
        sum0 += __shfl_xor_sync(0xFFFFFFFF, sum0, 2);
        sum1 += __shfl_xor_sync(0xFFFFFFFF, sum1, 1);
        sum1 += __shfl_xor_sync(0xFFFFFFFF, sum1, 2);
        l_r[0] = l_r[0] * al0 + sum0;
        l_r[1] = l_r[1] * al1 + sum1;

#pragma unroll
        for (int nt = 0; nt < 8; nt++) {
            oacc[nt][0] *= al0; oacc[nt][1] *= al0;
            oacc[nt][2] *= al1; oacc[nt][3] *= al1;
        }

#pragma unroll
        for (int kc = 0; kc < 4; kc++) {
            uint32_t pa[4];
            __half2 t0 = __floats2half2_rn(sacc[2 * kc][0],     sacc[2 * kc][1]);
            __half2 t1 = __floats2half2_rn(sacc[2 * kc][2],     sacc[2 * kc][3]);
            __half2 t2 = __floats2half2_rn(sacc[2 * kc + 1][0], sacc[2 * kc + 1][1]);
            __half2 t3 = __floats2half2_rn(sacc[2 * kc + 1][2], sacc[2 * kc + 1][3]);
            pa[0] = reinterpret_cast<uint32_t&>(t0);
            pa[1] = reinterpret_cast<uint32_t&>(t1);
            pa[2] = reinterpret_cast<uint32_t&>(t2);
            pa[3] = reinterpret_cast<uint32_t&>(t3);

            uint32_t vb[4][4];
#pragma unroll
            for (int g = 0; g < 4; g++)
                ldmatrix_x4_trans(vb[g][0], vb[g][1], vb[g][2], vb[g][3],
                                  smem_u32(&Vs[cur][kc * 16 + frow][g * 16 + fcol]));
#pragma unroll
            for (int nt = 0; nt < 8; nt++) {
                const int g = nt >> 1, hh = (nt & 1) * 2;
                mma_16816(oacc[nt], pa, vb[g][hh], vb[g][hh + 1]);
            }
        }
    }

    const float inv0 = 1.f / l_r[0];
    const float inv1 = 1.f / l_r[1];
    const size_t row_lo = rowbase + q0 + w * 16 + (l >> 2);
    const size_t row_hi = row_lo + 8;
#pragma unroll
    for (int nt = 0; nt < 8; nt++) {
        const int col = colq + nt * 8 + (l & 3) * 2;
        *(__half2*)(Og + row_lo * DMODEL + col) =
            __floats2half2_rn(oacc[nt][0] * inv0, oacc[nt][1] * inv0);
        *(__half2*)(Og + row_hi * DMODEL + col) =
            __floats2half2_rn(oacc[nt][2] * inv1, oacc[nt][3] * inv1);
    }
}

// ---------------------------------------------------------------------------
extern "C" void kernel_launch(void* const* d_in, const int* in_sizes, int n_in,
                              void* d_out, int out_size)
{
    const float* input = (const float*)d_in[0];
    const float* padm  = (const float*)d_in[1];
    const float* wq_w  = (const float*)d_in[2];
    const float* wq_b  = (const float*)d_in[3];
    const float* wk_w  = (const float*)d_in[4];
    const float* wk_b  = (const float*)d_in[5];
    const float* wv_w  = (const float*)d_in[6];
    const float* wv_b  = (const float*)d_in[7];
    const float* fin_w = (const float*)d_in[8];
    const float* fin_b = (const float*)d_in[9];
    float* out = (float*)d_out;

    __half *Qp, *Kp, *Vp, *Ap, *Xp, *Wq, *Wk, *Wv, *Wf;
    cudaGetSymbolAddress((void**)&Qp, g_Qh);
    cudaGetSymbolAddress((void**)&Kp, g_Kh);
    cudaGetSymbolAddress((void**)&Vp, g_Vh);
    cudaGetSymbolAddress((void**)&Ap, g_Ah);
    cudaGetSymbolAddress((void**)&Xp, g_Xh);
    cudaGetSymbolAddress((void**)&Wq, g_Wqh);
    cudaGetSymbolAddress((void**)&Wk, g_Wkh);
    cudaGetSymbolAddress((void**)&Wv, g_Wvh);
    cudaGetSymbolAddress((void**)&Wf, g_Wfh);

    // fp32 -> f16 converts (input + 4 weight matrices)
    const int nX = NROWS * DMODEL;      // 4194304
    const int nW = DMODEL * DMODEL;     // 1048576
    cvt_f32_f16_kernel<<<nX / (256 * 8), 256>>>(input, Xp, nX);
    cvt_f32_f16_kernel<<<nW / (256 * 8), 256>>>(wq_w, Wq, nW);
    cvt_f32_f16_kernel<<<nW / (256 * 8), 256>>>(wk_w, Wk, nW);
    cvt_f32_f16_kernel<<<nW / (256 * 8), 256>>>(wv_w, Wv, nW);
    cvt_f32_f16_kernel<<<nW / (256 * 8), 256>>>(fin_w, Wf, nW);

    dim3 gemm_grid(DMODEL / 128, NROWS / 128);  // (8, 32)

    // QKV projections (pure f16, cp.async double-buffered)
    hgemm_db_kernel<__half><<<gemm_grid, 256>>>(Xp, Wq, wq_b, Qp, NROWS, DMODEL, DMODEL);
    hgemm_db_kernel<__half><<<gemm_grid, 256>>>(Xp, Wk, wk_b, Kp, NROWS, DMODEL, DMODEL);
    hgemm_db_kernel<__half><<<gemm_grid, 256>>>(Xp, Wv, wv_b, Vp, NROWS, DMODEL, DMODEL);

    // Causal attention (f16 tensor-core flash, cp.async double-buffered)
    dim3 attn_grid(SLEN / 64, NHEAD, BATCH);   // (32, 16, 2)
    flash_attn_mma_kernel<<<attn_grid, 128>>>(Qp, Kp, Vp, padm, Ap);

    // Output projection (f16 in, fp32 out)
    hgemm_db_kernel<float><<<gemm_grid, 256>>>(Ap, Wf, fin_b, out, NROWS, DMODEL, DMODEL);
}